// round 2
// baseline (speedup 1.0000x reference)
#include <cuda_runtime.h>
#include <cuda_bf16.h>
#include <cstdint>

#define NN 10000
#define EE 320000
#define ET (EE + NN)
#define DIN 256

// ---------------- scratch (no allocations allowed) ----------------
__device__ float g_xl[NN * 256];
__device__ float g_xr[NN * 256];
__device__ float g_h0[NN * 256];
__device__ float g_h1[NN * 256];
__device__ float g_z [NN * 32];
__device__ int   g_deg[NN];
__device__ int   g_cur[NN];
__device__ int   g_off[NN + 1];
__device__ int   g_adj[ET];

// ---------------- CSR build ----------------
__global__ void zero_kernel(int* a, int* b, int n) {
    int i = blockIdx.x * blockDim.x + threadIdx.x;
    if (i < n) { a[i] = 0; b[i] = 0; }
}

__global__ void count_kernel(const int* __restrict__ ei, int* __restrict__ deg) {
    int t = blockIdx.x * blockDim.x + threadIdx.x;
    if (t >= ET) return;
    int d = (t < EE) ? ei[EE + t] : (t - EE);
    atomicAdd(&deg[d], 1);
}

__global__ void scan_kernel(const int* __restrict__ deg, int* __restrict__ off) {
    __shared__ int sums[1024];
    const int IPT = 10;  // 1024*10 >= NN+1
    int tid = threadIdx.x;
    int base = tid * IPT;
    int local[IPT];
    int s = 0;
#pragma unroll
    for (int i = 0; i < IPT; i++) {
        int idx = base + i;
        int v = (idx < NN) ? deg[idx] : 0;
        local[i] = s;
        s += v;
    }
    sums[tid] = s;
    __syncthreads();
    for (int o = 1; o < 1024; o <<= 1) {
        int v = (tid >= o) ? sums[tid - o] : 0;
        __syncthreads();
        sums[tid] += v;
        __syncthreads();
    }
    int pre = (tid == 0) ? 0 : sums[tid - 1];
#pragma unroll
    for (int i = 0; i < IPT; i++) {
        int idx = base + i;
        if (idx <= NN) off[idx] = pre + local[i];
    }
}

__global__ void scatter_kernel(const int* __restrict__ ei, const int* __restrict__ off,
                               int* __restrict__ cur, int* __restrict__ adj) {
    int t = blockIdx.x * blockDim.x + threadIdx.x;
    if (t >= ET) return;
    int s, d;
    if (t < EE) { s = ei[t]; d = ei[EE + t]; }
    else        { s = t - EE; d = s; }
    int pos = off[d] + atomicAdd(&cur[d], 1);
    adj[pos] = s;
}

// per-node insertion sort -> deterministic accumulation order
__global__ void sort_kernel(const int* __restrict__ off, int* __restrict__ adj) {
    int i = blockIdx.x * blockDim.x + threadIdx.x;
    if (i >= NN) return;
    int b = off[i], e = off[i + 1];
    for (int p = b + 1; p < e; p++) {
        int v = adj[p];
        int q = p - 1;
        while (q >= b && adj[q] > v) { adj[q + 1] = adj[q]; q--; }
        adj[q + 1] = v;
    }
}

// ---------------- 128x64 SIMT GEMM: C[M,Nc] = A[M,K] @ B[K,Nc] + bias ----------------
// requires Nc % 64 == 0, K % 16 == 0
__global__ void gemm128_bias_kernel(const float* __restrict__ A, const float* __restrict__ B,
                                    const float* __restrict__ bias, float* __restrict__ C,
                                    int M, int K, int Nc) {
    __shared__ float As[128][16];
    __shared__ float Bs[16][64];
    int tid = threadIdx.x;
    int tx = tid & 15, ty = tid >> 4;
    int i0 = blockIdx.y * 128, j0 = blockIdx.x * 64;
    float acc[8][4] = {};
    for (int k0 = 0; k0 < K; k0 += 16) {
#pragma unroll
        for (int l = 0; l < 8; l++) {
            int lin = tid + l * 256;
            int m = lin >> 4, k = lin & 15;
            int gm = i0 + m;
            As[m][k] = (gm < M) ? A[(size_t)gm * K + k0 + k] : 0.f;
        }
#pragma unroll
        for (int l = 0; l < 4; l++) {
            int lin = tid + l * 256;
            int k = lin >> 6, n = lin & 63;
            Bs[k][n] = B[(size_t)(k0 + k) * Nc + j0 + n];
        }
        __syncthreads();
#pragma unroll
        for (int k = 0; k < 16; k++) {
            float a[8], b[4];
            float4 bv = *(const float4*)&Bs[k][tx * 4];
            b[0] = bv.x; b[1] = bv.y; b[2] = bv.z; b[3] = bv.w;
#pragma unroll
            for (int i = 0; i < 8; i++) a[i] = As[ty * 8 + i][k];
#pragma unroll
            for (int i = 0; i < 8; i++)
#pragma unroll
                for (int j = 0; j < 4; j++) acc[i][j] += a[i] * b[j];
        }
        __syncthreads();
    }
    float4 bb = *(const float4*)&bias[j0 + tx * 4];
#pragma unroll
    for (int i = 0; i < 8; i++) {
        int gm = i0 + ty * 8 + i;
        if (gm < M) {
            float4 v;
            v.x = acc[i][0] + bb.x; v.y = acc[i][1] + bb.y;
            v.z = acc[i][2] + bb.z; v.w = acc[i][3] + bb.w;
            *(float4*)&C[(size_t)gm * Nc + j0 + tx * 4] = v;
        }
    }
}

// ---------------- 64x64 SIMT GEMM (for small Nc) ----------------
__global__ void gemm_bias_kernel(const float* __restrict__ A, const float* __restrict__ B,
                                 const float* __restrict__ bias, float* __restrict__ C,
                                 int M, int K, int Nc) {
    __shared__ float As[64][33];
    __shared__ float Bs[32][64];
    int tid = threadIdx.x;
    int tx = tid & 15, ty = tid >> 4;
    int i0 = blockIdx.y * 64, j0 = blockIdx.x * 64;
    float acc[4][4] = {};
    for (int k0 = 0; k0 < K; k0 += 32) {
#pragma unroll
        for (int l = 0; l < 8; l++) {
            int lin = tid + l * 256;
            int m = lin >> 5, k = lin & 31;
            int gm = i0 + m;
            As[m][k] = (gm < M) ? A[(size_t)gm * K + k0 + k] : 0.f;
        }
#pragma unroll
        for (int l = 0; l < 8; l++) {
            int lin = tid + l * 256;
            int k = lin >> 6, n = lin & 63;
            int gn = j0 + n;
            Bs[k][n] = (gn < Nc) ? B[(size_t)(k0 + k) * Nc + gn] : 0.f;
        }
        __syncthreads();
#pragma unroll
        for (int k = 0; k < 32; k++) {
            float a[4];
#pragma unroll
            for (int i = 0; i < 4; i++) a[i] = As[ty * 4 + i][k];
            float4 bv = *(const float4*)&Bs[k][tx * 4];
            float b[4] = {bv.x, bv.y, bv.z, bv.w};
#pragma unroll
            for (int i = 0; i < 4; i++)
#pragma unroll
                for (int j = 0; j < 4; j++) acc[i][j] += a[i] * b[j];
        }
        __syncthreads();
    }
    int gn = j0 + tx * 4;
    if (gn < Nc) {
        float4 bb = *(const float4*)&bias[gn];
#pragma unroll
        for (int i = 0; i < 4; i++) {
            int gm = i0 + ty * 4 + i;
            if (gm < M) {
                float4 v;
                v.x = acc[i][0] + bb.x; v.y = acc[i][1] + bb.y;
                v.z = acc[i][2] + bb.z; v.w = acc[i][3] + bb.w;
                *(float4*)&C[(size_t)gm * Nc + gn] = v;
            }
        }
    }
}

// ---------------- fused GATv2: stage xl chunk in smem, score + softmax + aggregate ----------------
template <int H, int C, int BLOCK, int CHUNK>
__global__ void gat_fused_kernel(const float* __restrict__ xl, const float* __restrict__ xr,
                                 const float* __restrict__ att, const float* __restrict__ bo,
                                 const int* __restrict__ off, const int* __restrict__ adj,
                                 float* __restrict__ out, int applyElu) {
    constexpr int HC = H * C;
    constexpr int NW = BLOCK / 32;
    constexpr int G  = BLOCK / HC;   // channel replica groups for aggregation
    constexpr int V  = HC / 4;       // float4 per row
    __shared__ float s_x[CHUNK][HC];
    __shared__ float s_xr[HC];
    __shared__ float s_att[HC];
    __shared__ int   s_src[CHUNK];
    __shared__ float s_sc[CHUNK * H];
    __shared__ float s_m[H], s_d[H], s_r[H];
    __shared__ float s_part[BLOCK];

    int node = blockIdx.x;
    int tid = threadIdx.x;
    int lane = tid & 31, wid = tid >> 5;
    int beg = off[node], end = off[node + 1];

    for (int t = tid; t < HC; t += BLOCK) {
        s_xr[t] = xr[(size_t)node * HC + t];
        s_att[t] = att[t];
    }
    if (tid < H) { s_m[tid] = -1e30f; s_d[tid] = 0.f; }

    int g = tid / HC, ch = tid % HC;
    int h = ch / C;
    float acc = 0.f;
    __syncthreads();

    for (int c0 = beg; c0 < end; c0 += CHUNK) {
        int n = min(CHUNK, end - c0);
        for (int t = tid; t < n; t += BLOCK) s_src[t] = adj[c0 + t];
        __syncthreads();

        // stage xl rows for this chunk (coalesced float4)
        for (int l = tid; l < n * V; l += BLOCK) {
            int e = l / V, col = l % V;
            ((float4*)s_x[e])[col] =
                ((const float4*)(xl + (size_t)s_src[e] * HC))[col];
        }
        __syncthreads();

        // warp-per-edge scores from smem
        for (int e = wid; e < n; e += NW) {
#pragma unroll
            for (int hh = 0; hh < H; hh++) {
                float p = 0.f;
#pragma unroll
                for (int c = lane; c < C; c += 32) {
                    float v = s_x[e][hh * C + c] + s_xr[hh * C + c];
                    v = v > 0.f ? v : 0.2f * v;
                    p += v * s_att[hh * C + c];
                }
#pragma unroll
                for (int o = 16; o > 0; o >>= 1) p += __shfl_xor_sync(0xffffffffu, p, o);
                if (lane == 0) s_sc[e * H + hh] = p;
            }
        }
        __syncthreads();

        // online softmax stats per head (warp hh)
        if (wid < H) {
            int hh = wid;
            float mloc = -1e30f;
            for (int e = lane; e < n; e += 32) mloc = fmaxf(mloc, s_sc[e * H + hh]);
#pragma unroll
            for (int o = 16; o > 0; o >>= 1) mloc = fmaxf(mloc, __shfl_xor_sync(0xffffffffu, mloc, o));
            float mold = s_m[hh];
            float mnew = fmaxf(mold, mloc);
            float r = __expf(mold - mnew);  // 0 on first chunk
            float sum = 0.f;
            for (int e = lane; e < n; e += 32) {
                float w = __expf(s_sc[e * H + hh] - mnew);
                s_sc[e * H + hh] = w;
                sum += w;
            }
#pragma unroll
            for (int o = 16; o > 0; o >>= 1) sum += __shfl_xor_sync(0xffffffffu, sum, o);
            if (lane == 0) { s_m[hh] = mnew; s_d[hh] = s_d[hh] * r + sum; s_r[hh] = r; }
        }
        __syncthreads();

        // weighted accumulation from smem: group g handles e = g, g+G, ...
        acc *= s_r[h];
        for (int e = g; e < n; e += G)
            acc += s_sc[e * H + h] * s_x[e][ch];
        __syncthreads();
    }

    if (G == 1) {
        float o = acc / (s_d[h] + 1e-16f) + bo[ch];
        if (applyElu) o = o > 0.f ? o : expm1f(o);
        out[(size_t)node * HC + ch] = o;
    } else {
        s_part[tid] = acc;
        __syncthreads();
        if (tid < HC) {
            float a = 0.f;
#pragma unroll
            for (int gg = 0; gg < G; gg++) a += s_part[gg * HC + tid];
            float o = a / (s_d[tid / C] + 1e-16f) + bo[tid];
            if (applyElu) o = o > 0.f ? o : expm1f(o);
            out[(size_t)node * HC + tid] = o;
        }
    }
}

// ---------------- reparameterize ----------------
__global__ void z_kernel(const float* __restrict__ mu, const float* __restrict__ lv,
                         const float* __restrict__ eps, float* __restrict__ z) {
    int i = blockIdx.x * blockDim.x + threadIdx.x;
    if (i < NN * 32) z[i] = mu[i] + eps[i] * __expf(0.5f * lv[i]);
}

// ---------------- adj = z @ z^T : 128x128 tile, 8x8 per thread ----------------
__global__ void zzt_kernel(const float* __restrict__ z, float* __restrict__ out) {
    __shared__ float Zit[32][132];
    __shared__ float Zjt[32][132];
    int tid = threadIdx.x;
    int tx = tid & 15, ty = tid >> 4;
    int i0 = blockIdx.y * 128, j0 = blockIdx.x * 128;
    for (int l = tid; l < 128 * 32; l += 256) {
        int r = l >> 5, k = l & 31;
        int gi = i0 + r, gj = j0 + r;
        Zit[k][r] = (gi < NN) ? z[(size_t)gi * 32 + k] : 0.f;
        Zjt[k][r] = (gj < NN) ? z[(size_t)gj * 32 + k] : 0.f;
    }
    __syncthreads();
    float acc[8][8] = {};
#pragma unroll
    for (int k = 0; k < 32; k++) {
        float a[8], b[8];
        *(float4*)&a[0] = *(const float4*)&Zit[k][ty * 8];
        *(float4*)&a[4] = *(const float4*)&Zit[k][ty * 8 + 4];
        *(float4*)&b[0] = *(const float4*)&Zjt[k][tx * 8];
        *(float4*)&b[4] = *(const float4*)&Zjt[k][tx * 8 + 4];
#pragma unroll
        for (int i = 0; i < 8; i++)
#pragma unroll
            for (int j = 0; j < 8; j++) acc[i][j] += a[i] * b[j];
    }
#pragma unroll
    for (int i = 0; i < 8; i++) {
        int gi = i0 + ty * 8 + i;
        if (gi < NN) {
            float* row = out + (size_t)gi * NN;
            int gj = j0 + tx * 8;
            if (gj < NN) {
                float4 v = {acc[i][0], acc[i][1], acc[i][2], acc[i][3]};
                *(float4*)&row[gj] = v;
            }
            if (gj + 4 < NN) {
                float4 v = {acc[i][4], acc[i][5], acc[i][6], acc[i][7]};
                *(float4*)&row[gj + 4] = v;
            }
        }
    }
}

// ---------------- launch ----------------
extern "C" void kernel_launch(void* const* d_in, const int* in_sizes, int n_in,
                              void* d_out, int out_size) {
    const float* x   = (const float*)d_in[0];
    const int*   ei  = (const int*)d_in[1];
    const float* eps = (const float*)d_in[2];

    const float* Wl0 = (const float*)d_in[3];
    const float* bl0 = (const float*)d_in[4];
    const float* Wr0 = (const float*)d_in[5];
    const float* br0 = (const float*)d_in[6];
    const float* at0 = (const float*)d_in[7];
    const float* bo0 = (const float*)d_in[8];

    const float* Wl1 = (const float*)d_in[9];
    const float* bl1 = (const float*)d_in[10];
    const float* Wr1 = (const float*)d_in[11];
    const float* br1 = (const float*)d_in[12];
    const float* at1 = (const float*)d_in[13];
    const float* bo1 = (const float*)d_in[14];

    const float* Wlm = (const float*)d_in[15];
    const float* blm = (const float*)d_in[16];
    const float* Wrm = (const float*)d_in[17];
    const float* brm = (const float*)d_in[18];
    const float* atm = (const float*)d_in[19];
    const float* bom = (const float*)d_in[20];

    const float* Wlv = (const float*)d_in[21];
    const float* blv = (const float*)d_in[22];
    const float* Wrv = (const float*)d_in[23];
    const float* brv = (const float*)d_in[24];
    const float* atv = (const float*)d_in[25];
    const float* bov = (const float*)d_in[26];

    float* out    = (float*)d_out;
    float* out_mu = out + (size_t)NN * NN;
    float* out_lv = out_mu + (size_t)NN * 32;

    void *pxl, *pxr, *ph0, *ph1, *pz, *pdeg, *pcur, *poff, *padj;
    cudaGetSymbolAddress(&pxl, g_xl);
    cudaGetSymbolAddress(&pxr, g_xr);
    cudaGetSymbolAddress(&ph0, g_h0);
    cudaGetSymbolAddress(&ph1, g_h1);
    cudaGetSymbolAddress(&pz, g_z);
    cudaGetSymbolAddress(&pdeg, g_deg);
    cudaGetSymbolAddress(&pcur, g_cur);
    cudaGetSymbolAddress(&poff, g_off);
    cudaGetSymbolAddress(&padj, g_adj);

    float* xl = (float*)pxl; float* xr = (float*)pxr;
    float* h0 = (float*)ph0; float* h1 = (float*)ph1;
    float* zp = (float*)pz;
    int* deg = (int*)pdeg; int* cur = (int*)pcur;
    int* off = (int*)poff; int* adj = (int*)padj;

    // CSR build (deterministic after per-node sort)
    zero_kernel<<<(NN + 255) / 256, 256>>>(deg, cur, NN);
    count_kernel<<<(ET + 255) / 256, 256>>>(ei, deg);
    scan_kernel<<<1, 1024>>>(deg, off);
    scatter_kernel<<<(ET + 255) / 256, 256>>>(ei, off, cur, adj);
    sort_kernel<<<(NN + 127) / 128, 128>>>(off, adj);

    dim3 gBig(256 / 64, (NN + 127) / 128);   // 4 x 79
    dim3 gSml(1, (NN + 63) / 64);            // Nc=32 via 64x64 kernel

    // layer 0
    gemm128_bias_kernel<<<gBig, 256>>>(x, Wl0, bl0, xl, NN, DIN, 256);
    gemm128_bias_kernel<<<gBig, 256>>>(x, Wr0, br0, xr, NN, DIN, 256);
    gat_fused_kernel<4, 64, 256, 40><<<NN, 256>>>(xl, xr, at0, bo0, off, adj, h0, 1);

    // layer 1
    gemm128_bias_kernel<<<gBig, 256>>>(h0, Wl1, bl1, xl, NN, 256, 256);
    gemm128_bias_kernel<<<gBig, 256>>>(h0, Wr1, br1, xr, NN, 256, 256);
    gat_fused_kernel<4, 64, 256, 40><<<NN, 256>>>(xl, xr, at1, bo1, off, adj, h1, 1);

    // mu head
    gemm_bias_kernel<<<gSml, 256>>>(h1, Wlm, blm, xl, NN, 256, 32);
    gemm_bias_kernel<<<gSml, 256>>>(h1, Wrm, brm, xr, NN, 256, 32);
    gat_fused_kernel<1, 32, 128, 128><<<NN, 128>>>(xl, xr, atm, bom, off, adj, out_mu, 0);

    // log_var head
    gemm_bias_kernel<<<gSml, 256>>>(h1, Wlv, blv, xl, NN, 256, 32);
    gemm_bias_kernel<<<gSml, 256>>>(h1, Wrv, brv, xr, NN, 256, 32);
    gat_fused_kernel<1, 32, 128, 128><<<NN, 128>>>(xl, xr, atv, bov, off, adj, out_lv, 0);

    // reparameterize + dense decode
    z_kernel<<<(NN * 32 + 255) / 256, 256>>>(out_mu, out_lv, eps, zp);
    zzt_kernel<<<dim3((NN + 127) / 128, (NN + 127) / 128), 256>>>(zp, out);
}